// round 7
// baseline (speedup 1.0000x reference)
#include <cuda_runtime.h>
#include <cuda_fp16.h>
#include <cstdint>

// GRU decoder, H=4096, T=2048. Persistent single kernel + software grid barrier.
// R2: fp16 weight scratch (100.7 MB) -> L2-resident working set.
// R6: compiler-batched loads + fast gates.                       [25.40 ms]
// R7: cp.async.cg weight pipeline (L2 -> smem, 4-stage ring per warp):
//     - in-flight bytes no longer limited by the 72-reg ceiling
//     - weight loads stream ACROSS the grid barrier (chunks of step t+1
//       issued during step t's tail) -> barrier/staging bubble filled
//     - cg bypasses L1 (read-once data; relieves L1 wavefront pressure)

#define HDIM 4096
#define IN_DIM 400
#define OROWS 401
#define NOUT 400
#define WARPS_PER_BLOCK 28
#define NTHREADS (WARPS_PER_BLOCK * 32)

#define NSTAGE 4
#define NCHUNK 16
// per warp, per stage: 3 streams x 32 lanes x 16 B = 1536 B
#define STAGE_BYTES 1536
#define WARP_BUF_BYTES (NSTAGE * STAGE_BYTES)          // 6144
#define SMEM_H_BYTES (HDIM * 4)                        // 16384
#define SMEM_TOTAL (SMEM_H_BYTES + WARPS_PER_BLOCK * WARP_BUF_BYTES)  // 188416

__device__ __half g_whh_h[(size_t)3 * HDIM * HDIM];   // 100.7 MB fp16 W_hh
__device__ __half g_wout_h[(size_t)OROWS * HDIM];     // 3.3 MB fp16 W_out
__device__ float g_h[2][HDIM];
__device__ float g_gx[3 * HDIM];
__device__ unsigned g_cnt;
__device__ unsigned g_gen;

__device__ __forceinline__ float warp_sum(float v) {
#pragma unroll
    for (int o = 16; o; o >>= 1) v += __shfl_xor_sync(0xffffffffu, v, o);
    return v;
}

__device__ __forceinline__ void grid_sync() {
    __syncthreads();
    if (threadIdx.x == 0) {
        __threadfence();
        unsigned gen = *(volatile unsigned*)&g_gen;
        unsigned nblk = gridDim.x;
        if (atomicAdd(&g_cnt, 1u) == nblk - 1u) {
            atomicExch(&g_cnt, 0u);
            __threadfence();
            atomicAdd(&g_gen, 1u);
        } else {
            while (*(volatile unsigned*)&g_gen == gen) { __nanosleep(32); }
        }
        __threadfence();
    }
    __syncthreads();
}

__device__ __forceinline__ float fast_sigmoid(float x) {
    float e;
    asm("ex2.approx.f32 %0, %1;" : "=f"(e) : "f"(-1.4426950408889634f * x));
    float r;
    asm("rcp.approx.f32 %0, %1;" : "=f"(r) : "f"(1.0f + e));
    return r;
}
__device__ __forceinline__ float fast_tanh(float x) {
    float r;
    asm("tanh.approx.f32 %0, %1;" : "=f"(r) : "f"(x));
    return r;
}

__device__ __forceinline__ void cp16(uint32_t smem_dst, const void* gsrc) {
    asm volatile("cp.async.cg.shared.global [%0], [%1], 16;"
                 :: "r"(smem_dst), "l"(gsrc));
}
__device__ __forceinline__ void cp_commit() {
    asm volatile("cp.async.commit_group;");
}
__device__ __forceinline__ void cp_wait3() {
    asm volatile("cp.async.wait_group 3;" ::: "memory");
}

// dot of 8 fp16 weights (as uint4) with 8 fp32 h values, fp32 accumulate
__device__ __forceinline__ float dot8(uint4 u, float4 hA, float4 hB) {
    float2 p; float s0 = 0.f, s1 = 0.f;
    p = __half22float2(*(const __half2*)&u.x); s0 += p.x * hA.x; s1 += p.y * hA.y;
    p = __half22float2(*(const __half2*)&u.y); s0 += p.x * hA.z; s1 += p.y * hA.w;
    p = __half22float2(*(const __half2*)&u.z); s0 += p.x * hB.x; s1 += p.y * hB.y;
    p = __half22float2(*(const __half2*)&u.w); s0 += p.x * hB.z; s1 += p.y * hB.w;
    return s0 + s1;
}

__global__ void __launch_bounds__(NTHREADS, 1)
decoder_persistent_kernel(const float* __restrict__ start,
                          const float* __restrict__ enc,
                          const float* __restrict__ W_ih,
                          const float* __restrict__ W_hh,
                          const float* __restrict__ b_ih,
                          const float* __restrict__ b_hh,
                          const float* __restrict__ W_out,
                          const float* __restrict__ b_out,
                          const int*   __restrict__ maxlen_ptr,
                          float* __restrict__ out)
{
    extern __shared__ char smem_dyn[];
    float* h_s = (float*)smem_dyn;
    __half* mybuf = (__half*)(smem_dyn + SMEM_H_BYTES) +
                    (threadIdx.x >> 5) * (WARP_BUF_BYTES / 2);

    const int lane   = threadIdx.x & 31;
    const int warp   = threadIdx.x >> 5;
    const int gwarp  = blockIdx.x * WARPS_PER_BLOCK + warp;
    const int gwarps = gridDim.x * WARPS_PER_BLOCK;
    const int gtid    = blockIdx.x * NTHREADS + threadIdx.x;
    const int gthreads = gridDim.x * NTHREADS;
    const int T = maxlen_ptr ? *maxlen_ptr : 2048;

    // ---- convert W_hh, W_out to fp16 scratch ----
    {
        const size_t total = (size_t)3 * HDIM * HDIM;
        for (size_t idx = (size_t)gtid * 4; idx < total; idx += (size_t)gthreads * 4) {
            float4 v = *(const float4*)(W_hh + idx);
            __half2* dst = (__half2*)(g_whh_h + idx);
            dst[0] = __floats2half2_rn(v.x, v.y);
            dst[1] = __floats2half2_rn(v.z, v.w);
        }
        const size_t ototal = (size_t)OROWS * HDIM;
        for (size_t idx = (size_t)gtid * 4; idx < ototal; idx += (size_t)gthreads * 4) {
            float4 v = *(const float4*)(W_out + idx);
            __half2* dst = (__half2*)(g_wout_h + idx);
            dst[0] = __floats2half2_rn(v.x, v.y);
            dst[1] = __floats2half2_rn(v.z, v.w);
        }
    }

    for (int idx = gtid; idx < HDIM; idx += gthreads)
        g_h[0][idx] = enc[idx];

    for (int r = gwarp; r < 3 * HDIM; r += gwarps) {
        const float* wr = W_ih + (size_t)r * IN_DIM;
        float acc = 0.f;
        for (int k = lane; k < IN_DIM; k += 32) {
            float x = start[k];
            x = x > 0.f ? x : 0.f;
            acc += wr[k] * x;
        }
        acc = warp_sum(acc);
        if (lane == 0) g_gx[r] = acc + b_ih[r];
    }
    grid_sync();

    int spread = gwarps / OROWS;
    if (spread < 1) spread = 1;
    int brow = -1;
    if ((gwarp % spread) == 0 && (gwarp / spread) < OROWS) brow = gwarp / spread;

    const int myrow = (gwarp < HDIM) ? gwarp : -1;

    float c_br = 0.f, c_bz = 0.f, c_bn = 0.f, c_gr = 0.f, c_gz = 0.f, c_gn = 0.f;
    if (myrow >= 0) {
        c_br = b_hh[myrow];
        c_bz = b_hh[myrow + HDIM];
        c_bn = b_hh[myrow + 2 * HDIM];
        c_gr = g_gx[myrow];
        c_gz = g_gx[myrow + HDIM];
        c_gn = g_gx[myrow + 2 * HDIM];
    }
    const float c_bo = (brow >= 0) ? b_out[brow] : 0.f;

    // weight row base pointers (fixed per warp)
    const __half* w0 = (myrow >= 0) ? g_whh_h + (size_t)myrow * HDIM : g_whh_h;
    const __half* w1 = (myrow >= 0) ? g_whh_h + ((size_t)myrow + HDIM) * HDIM : g_whh_h;
    const __half* w2 = (myrow >= 0) ? g_whh_h + ((size_t)myrow + 2 * HDIM) * HDIM : g_whh_h;

    // smem ring addresses for this warp/lane (byte addresses in shared space)
    const uint32_t sh_base = (uint32_t)__cvta_generic_to_shared(mybuf) + lane * 16;

    // issue chunk c (weights only; independent of h/barrier)
    auto issue_chunk = [&](int c) {
        int slot = c & (NSTAGE - 1);
        uint32_t d = sh_base + slot * STAGE_BYTES;
        int off = c * 256 + lane * 8;         // half index within row
        cp16(d,        w0 + off);
        cp16(d + 512,  w1 + off);
        cp16(d + 1024, w2 + off);
        cp_commit();
    };

    // prologue: fill the pipeline for step 0
    if (myrow >= 0) {
#pragma unroll
        for (int c = 0; c < NSTAGE; c++) issue_chunk(c);
    }

    for (int t = 0; t < T; t++) {
        const float* __restrict__ hc = g_h[t & 1];
        float* __restrict__ hn = g_h[(t + 1) & 1];

        {
            const float4* src = (const float4*)hc;
            float4* dst = (float4*)h_s;
            for (int idx = threadIdx.x; idx < HDIM / 4; idx += NTHREADS)
                dst[idx] = src[idx];
        }
        __syncthreads();

        if (myrow >= 0) {
            const float4* h4 = (const float4*)h_s;
            float a0 = 0.f, a1 = 0.f, a2 = 0.f;
#pragma unroll
            for (int c = 0; c < NCHUNK; c++) {
                cp_wait3();                    // chunk c landed in its slot
                int slot = c & (NSTAGE - 1);
                const __half* sp = mybuf + (size_t)slot * (STAGE_BYTES / 2) + lane * 8;
                uint4 u0 = *(const uint4*)(sp);
                uint4 u1 = *(const uint4*)(sp + 256);
                uint4 u2 = *(const uint4*)(sp + 512);
                float4 hA = h4[c * 64 + lane * 2];
                float4 hB = h4[c * 64 + lane * 2 + 1];
                a0 += dot8(u0, hA, hB);
                a1 += dot8(u1, hA, hB);
                a2 += dot8(u2, hA, hB);
                // refill slot with chunk c+4 (wraps into next step's chunks
                // for c >= 12 -> weight stream crosses the grid barrier)
                issue_chunk((c + NSTAGE) & (NCHUNK - 1));
            }
            a0 = warp_sum(a0);
            a1 = warp_sum(a1);
            a2 = warp_sum(a2);
            float r = fast_sigmoid(c_gr + a0 + c_br);
            float z = fast_sigmoid(c_gz + a1 + c_bz);
            float n = fast_tanh(c_gn + r * (a2 + c_bn));
            if (lane == 0) {
                hn[myrow] = (1.f - z) * n + z * h_s[myrow];
            }
        }

        // Stage B (deferred, for step t-1): h_new(t-1) == h_s; pre-barrier.
        if (t > 0 && brow >= 0) {
            const uint4* wr = (const uint4*)(g_wout_h + (size_t)brow * HDIM);
            const float4* h4 = (const float4*)h_s;
            float acc = 0.f;
#pragma unroll 4
            for (int k = lane; k < HDIM / 8; k += 32) {
                uint4 u = wr[k];
                acc += dot8(u, h4[2 * k], h4[2 * k + 1]);
            }
            acc = warp_sum(acc);
            if (lane == 0) {
                float o = acc + c_bo;
                int tt = t - 1;
                if (brow < NOUT)
                    out[(size_t)tt * NOUT + brow] = fast_tanh(o);
                else
                    out[(size_t)T * NOUT + tt] = fast_sigmoid(o);
            }
        }

        grid_sync();
    }

    // ---- final Stage B for step T-1 ----
    if (brow >= 0) {
        const float* hf = g_h[T & 1];
        const uint4* wr = (const uint4*)(g_wout_h + (size_t)brow * HDIM);
        const float4* h4 = (const float4*)hf;
        float acc = 0.f;
#pragma unroll 4
        for (int k = lane; k < HDIM / 8; k += 32) {
            uint4 u = wr[k];
            acc += dot8(u, h4[2 * k], h4[2 * k + 1]);
        }
        acc = warp_sum(acc);
        if (lane == 0) {
            float o = acc + c_bo;
            int tt = T - 1;
            if (brow < NOUT)
                out[(size_t)tt * NOUT + brow] = fast_tanh(o);
            else
                out[(size_t)T * NOUT + tt] = fast_sigmoid(o);
        }
    }
}

extern "C" void kernel_launch(void* const* d_in, const int* in_sizes, int n_in,
                              void* d_out, int out_size) {
    (void)in_sizes; (void)out_size;

    int dev = 0;
    cudaGetDevice(&dev);
    int sm = 148;
    cudaDeviceGetAttribute(&sm, cudaDevAttrMultiProcessorCount, dev);
    if (sm < 1) sm = 148;
    if (sm > 512) sm = 512;

    cudaFuncSetAttribute(decoder_persistent_kernel,
                         cudaFuncAttributeMaxDynamicSharedMemorySize, SMEM_TOTAL);

    const float* start = (const float*)d_in[0];
    const float* enc   = (const float*)d_in[1];
    const float* W_ih  = (const float*)d_in[2];
    const float* W_hh  = (const float*)d_in[3];
    const float* b_ih  = (const float*)d_in[4];
    const float* b_hh  = (const float*)d_in[5];
    const float* W_out = (const float*)d_in[6];
    const float* b_out = (const float*)d_in[7];
    const int* maxlen  = (n_in > 8) ? (const int*)d_in[8] : nullptr;

    decoder_persistent_kernel<<<sm, NTHREADS, SMEM_TOTAL>>>(
        start, enc, W_ih, W_hh, b_ih, b_hh, W_out, b_out, maxlen, (float*)d_out);
}